// round 16
// baseline (speedup 1.0000x reference)
#include <cuda_runtime.h>

// ---------------------------------------------------------------------------
// 5-layer stacked LSTM, H=51, B=256, T=2048. Output depends only on layer-3 h
// => layers 4,5 dead. 3 roles (L1,L2,L3) x 32 batch groups = 96 CTAs.
// R15 structure with ARBITER-PRIORITY REMAP (hi-wid-first scheduler):
//   comm warp (warp 0):   ring prefetch D=4 (latency-tolerant -> lowest prio)
//   I group (warps 1-7):  input GEMV(s), 2 rows x half-k per lane
//   R group (warps 8-14): recurrent GEMV(t) -> cell(t)  [serial chain -> TOP prio]
// gin 2 partials, 4-deep I->R handoff, tanh.approx (sigmoid x/2 folded),
// c in registers. Dataflow identical to R15; only warp roles permuted.
// ---------------------------------------------------------------------------

#define HN 51
#define NJ 204
#define TN 2048
#define NG 32
#define BT 8
#define NSLOT 16
#define XBUF 8
#define DPRE 4
#define NTH 480
#define IB   32               // first tid of I group  (warps 1-7)
#define RB   256              // first tid of R group  (warps 8-14)
#define EBT  408              // HN*BT
#define GSZ  1632             // NJ*BT

// named barrier ids / counts
#define B_IN0 2               // ids 2..5  : gin(s) ready     (I arrive, R sync)
#define B_FR0 6               // ids 6..9  : gin slot free    (R arrive, I sync)
#define B_RH  10              // R-internal: h(t) complete
#define B_XC  11              // I+comm pacing
#define CNT_RI 448
#define CNT_R  224
#define CNT_XC 256

typedef unsigned long long ull;

__device__ float    g_hbuf[2][NG][NSLOT][EBT];
__device__ unsigned g_prod[2][NG];
__device__ unsigned g_cons[2][NG];

__device__ __forceinline__ unsigned ld_acq(const unsigned* p) {
    unsigned v;
    asm volatile("ld.global.acquire.gpu.u32 %0, [%1];" : "=r"(v) : "l"(p));
    return v;
}
__device__ __forceinline__ void st_rel(unsigned* p, unsigned v) {
    asm volatile("st.global.release.gpu.u32 [%0], %1;" :: "l"(p), "r"(v));
}
__device__ __forceinline__ void wait_ge(unsigned* p, unsigned v) {
    if (ld_acq(p) >= v) return;
    while (ld_acq(p) < v) __nanosleep(32);
}
__device__ __forceinline__ float4 ldcg4(const float4* p) {
    float4 v;
    asm volatile("ld.global.cg.v4.f32 {%0,%1,%2,%3}, [%4];"
                 : "=f"(v.x), "=f"(v.y), "=f"(v.z), "=f"(v.w) : "l"(p));
    return v;
}
__device__ __forceinline__ ull ffma2(ull a, ull b, ull c) {
    ull d;
    asm("fma.rn.f32x2 %0, %1, %2, %3;" : "=l"(d) : "l"(a), "l"(b), "l"(c));
    return d;
}
__device__ __forceinline__ ull splat2(float x) {
    ull d; unsigned u = __float_as_uint(x);
    asm("mov.b64 %0, {%1, %2};" : "=l"(d) : "r"(u), "r"(u));
    return d;
}
__device__ __forceinline__ float tanha(float x) {
    float y;
    asm("tanh.approx.f32 %0, %1;" : "=f"(y) : "f"(x));
    return y;
}
__device__ __forceinline__ float sig_h(float y) {   // arg pre-halved
    return fmaf(0.5f, tanha(y), 0.5f);
}
#define BAR_SYNC(id, cnt)   asm volatile("bar.sync %0, %1;"   :: "r"(id), "r"(cnt) : "memory")
#define BAR_ARRIVE(id, cnt) asm volatile("bar.arrive %0, %1;" :: "r"(id), "r"(cnt) : "memory")
#define MEMBAR_CTA()        asm volatile("membar.cta;" ::: "memory")

__global__ void __launch_bounds__(64, 1) reset_kernel() {
    int i = threadIdx.x;
    if (i < NG) {
        g_prod[0][i] = 0; g_prod[1][i] = 0;
        g_cons[0][i] = 0; g_cons[1][i] = 0;
    }
}

__global__ void __launch_bounds__(NTH, 1) lstm_kernel(
    const float* __restrict__ x,    const float* __restrict__ Wih1,
    const float* __restrict__ Whh1, const float* __restrict__ bih1,
    const float* __restrict__ bhh1, const float* __restrict__ Wih,
    const float* __restrict__ Whh,  const float* __restrict__ bih,
    const float* __restrict__ bhh,  const float* __restrict__ Wl,
    const float* __restrict__ bl,   float* __restrict__ out)
{
    extern __shared__ float sm[];
    float* grec = sm;                 // [2 kh][GSZ]            3264
    float* gin  = sm + 3264;          // [4 par][2 kh][GSZ]     13056
    float* xin  = sm + 16320;         // [XBUF][52*8]           3328 (row 51 zero)
    float* h_t  = sm + 19648;         // [52*8] (row 51 zero)   416
    float* xchk = sm + 20064;         // [2][32][8]             512
    float* wl_s = sm + 20576;         // [52]
    // total 20628 floats = 82512 bytes

    const int tid  = threadIdx.x;
    const int role = blockIdx.x / NG;   // 0=L1, 1=L2, 2=L3
    const int g    = blockIdx.x % NG;

    const bool is_comm = (tid < IB);          // warp 0
    const bool is_I    = (tid >= IB && tid < RB);   // warps 1-7
    const int  itid    = is_I ? (tid - IB) : 0;     // 0..223
    const int  rtid    = (tid >= RB) ? (tid - RB) : 0;  // 0..223

    // ---------------- group-specific weight loads ----------------
    // Both R and I lanes: 2 gate rows x half-k (26 iters, k=25 overlap zeroed
    // in the kh=1 half). i,f,o rows pre-scaled by 0.5 for tanh-only sigmoid.
    float w0[26], w1[26];
    ull biasA = 0, biasB = 0, w1A = 0, w1B = 0;
    int kb = 0, r0 = 0;

    if (tid >= RB && rtid < 204) {        // R GEMV lane (recurrent weights)
        const int kh = rtid / 102, jp = rtid % 102;
        r0 = 2 * jp; kb = kh * 25;
        const float* W = (role == 0) ? Whh1 : (Whh + (role - 1) * NJ * HN);
        const float sc0 = ((r0     / 51) == 2) ? 1.f : 0.5f;
        const float sc1 = (((r0+1) / 51) == 2) ? 1.f : 0.5f;
        #pragma unroll
        for (int kk = 0; kk < 26; kk++) {
            int k = kb + kk;
            bool z = (kh == 1 && kk == 0);
            w0[kk] = z ? 0.f : sc0 * W[ r0      * HN + k];
            w1[kk] = z ? 0.f : sc1 * W[(r0 + 1) * HN + k];
        }
    } else if (is_I && itid < 204) {      // I GEMV lane (input weights)
        const int kh = itid / 102, jp = itid % 102;
        r0 = 2 * jp; kb = kh * 25;
        const float sc0 = ((r0     / 51) == 2) ? 1.f : 0.5f;
        const float sc1 = (((r0+1) / 51) == 2) ? 1.f : 0.5f;
        if (role > 0) {
            const int l = role - 1;
            const float* W = Wih + l * NJ * HN;
            #pragma unroll
            for (int kk = 0; kk < 26; kk++) {
                int k = kb + kk;
                bool z = (kh == 1 && kk == 0);
                w0[kk] = z ? 0.f : sc0 * W[ r0      * HN + k];
                w1[kk] = z ? 0.f : sc1 * W[(r0 + 1) * HN + k];
            }
            if (kh == 0) {
                biasA = splat2(sc0 * (bih[l * NJ + r0]     + bhh[l * NJ + r0]));
                biasB = splat2(sc1 * (bih[l * NJ + r0 + 1] + bhh[l * NJ + r0 + 1]));
            }
        } else if (kh == 0) {   // role 0: rank-1 input term
            w1A   = splat2(sc0 * Wih1[r0]);
            w1B   = splat2(sc1 * Wih1[r0 + 1]);
            biasA = splat2(sc0 * (bih1[r0]     + bhh1[r0]));
            biasB = splat2(sc1 * (bih1[r0 + 1] + bhh1[r0 + 1]));
        }
    }
    const float blv = (role == 2) ? bl[0] : 0.f;

    for (int i = tid; i < 20628; i += NTH) sm[i] = 0.f;
    __syncthreads();
    if (role == 2 && tid < HN) wl_s[tid] = Wl[tid];
    __syncthreads();

    float*       ring_out = (role < 2) ? &g_hbuf[role][g][0][0]     : (float*)0;
    const float* ring_in  = (role > 0) ? &g_hbuf[role - 1][g][0][0] : (const float*)0;

    // ---- prologue: comm warp fills xin slots 0..3 / x window 0 ----
    if (is_comm) {
        const int lane = tid;
        if (role > 0) {
            for (int d = 0; d < DPRE; d++) {
                if (lane == 0) wait_ge(&g_prod[role - 1][g], (unsigned)(d + 1));
                __syncwarp();
                const float4* s4 = (const float4*)(ring_in + d * EBT);
                float4* d4 = (float4*)(xin + d * 416);
                for (int i = lane; i < EBT / 4; i += 32) d4[i] = ldcg4(s4 + i);
                __syncwarp();
                if (lane == 0) st_rel(&g_cons[role - 1][g], (unsigned)(d + 1));
            }
        } else {
            #pragma unroll
            for (int b = 0; b < BT; b++)
                xchk[lane * 8 + b] = x[(size_t)(g * BT + b) * TN + lane];
        }
    }
    __syncthreads();

    // =====================================================================
    if (tid >= RB) {
        // ============= R group (warps 8-14: TOP arbiter priority) =========
        float c_a = 0.f, c_b = 0.f;
        const int  kh = (rtid < 204) ? rtid / 102 : 0;
        const bool lane_out = (role == 2) && (rtid >= 204 && rtid < 212);
        const bool lane_bp  = (role <  2) && (rtid == 212);

        for (int t = 0; t < TN; t++) {
            // ---- recurrent GEMV(t) over h(t-1) ----
            if (rtid < 204) {
                const ulonglong2* hp = (const ulonglong2*)(h_t + kb * BT);
                ull a00 = 0, a01 = 0, a02 = 0, a03 = 0;
                ull a10 = 0, a11 = 0, a12 = 0, a13 = 0;
                #pragma unroll
                for (int kk = 0; kk < 26; kk++) {
                    ulonglong2 S0 = hp[2 * kk], S1 = hp[2 * kk + 1];
                    ull q0 = splat2(w0[kk]);
                    ull q1 = splat2(w1[kk]);
                    a00 = ffma2(S0.x, q0, a00); a01 = ffma2(S0.y, q0, a01);
                    a02 = ffma2(S1.x, q0, a02); a03 = ffma2(S1.y, q0, a03);
                    a10 = ffma2(S0.x, q1, a10); a11 = ffma2(S0.y, q1, a11);
                    a12 = ffma2(S1.x, q1, a12); a13 = ffma2(S1.y, q1, a13);
                }
                float* gr = grec + kh * GSZ + r0 * BT;
                ulonglong2 s;
                s.x = a00; s.y = a01; *(ulonglong2*)(gr)          = s;
                s.x = a02; s.y = a03; *(ulonglong2*)(gr + 4)      = s;
                s.x = a10; s.y = a11; *(ulonglong2*)(gr + BT)     = s;
                s.x = a12; s.y = a13; *(ulonglong2*)(gr + BT + 4) = s;
            } else {
                if (lane_out && t > 0) {                 // out(t-1) from h(t-1)
                    const int b = rtid - 204;
                    float a = blv;
                    #pragma unroll
                    for (int u = 0; u < HN; u++) a += h_t[u * BT + b] * wl_s[u];
                    out[(size_t)(g * BT + b) * TN + (t - 1)] = a;
                }
                if (lane_bp && t >= NSLOT)
                    wait_ge(&g_cons[role][g], (unsigned)(t - (NSLOT - 1)));
            }

            BAR_SYNC(B_IN0 + (t & 3), CNT_RI);   // gin(t) ready; grec drained

            // ---- cell(t): elements rtid and rtid+224 (16 LDS/elem) ----
            {
                const float* gi = gin + (t & 3) * 2 * GSZ;
                float* rslot = (role < 2) ? (ring_out + (t & (NSLOT - 1)) * EBT)
                                          : (float*)0;
                {
                    const int e = rtid;
                    float yi = (grec[e]        + grec[GSZ + e])
                             + (gi[e]          + gi[GSZ + e]);
                    float yf = (grec[408 + e]  + grec[GSZ + 408 + e])
                             + (gi[408 + e]    + gi[GSZ + 408 + e]);
                    float gg = (grec[816 + e]  + grec[GSZ + 816 + e])
                             + (gi[816 + e]    + gi[GSZ + 816 + e]);
                    float yo = (grec[1224 + e] + grec[GSZ + 1224 + e])
                             + (gi[1224 + e]   + gi[GSZ + 1224 + e]);
                    float c = sig_h(yf) * c_a + sig_h(yi) * tanha(gg);
                    float h = sig_h(yo) * tanha(c);
                    c_a = c; h_t[e] = h;
                    if (role < 2) rslot[e] = h;
                }
                if (rtid < 184) {
                    const int e = rtid + 224;
                    float yi = (grec[e]        + grec[GSZ + e])
                             + (gi[e]          + gi[GSZ + e]);
                    float yf = (grec[408 + e]  + grec[GSZ + 408 + e])
                             + (gi[408 + e]    + gi[GSZ + 408 + e]);
                    float gg = (grec[816 + e]  + grec[GSZ + 816 + e])
                             + (gi[816 + e]    + gi[GSZ + 816 + e]);
                    float yo = (grec[1224 + e] + grec[GSZ + 1224 + e])
                             + (gi[1224 + e]   + gi[GSZ + 1224 + e]);
                    float c = sig_h(yf) * c_b + sig_h(yi) * tanha(gg);
                    float h = sig_h(yo) * tanha(c);
                    c_b = c; h_t[e] = h;
                    if (role < 2) rslot[e] = h;
                }
            }

            BAR_ARRIVE(B_FR0 + (t & 3), CNT_RI); // gin slot (t&3) consumed
            BAR_SYNC(B_RH, CNT_R);               // h(t) + ring STGs complete
            if (role < 2 && rtid == 0) st_rel(&g_prod[role][g], (unsigned)(t + 1));
        }
        // epilogue: out(TN-1)
        if (lane_out) {
            const int b = rtid - 204;
            float a = blv;
            #pragma unroll
            for (int u = 0; u < HN; u++) a += h_t[u * BT + b] * wl_s[u];
            out[(size_t)(g * BT + b) * TN + (TN - 1)] = a;
        }
    } else if (is_I) {
        // ================ I group (warps 1-7) =============================
        const int kh = (itid < 204) ? itid / 102 : 0;

        for (int s = 0; s < TN; s++) {
            BAR_SYNC(B_XC, CNT_XC);                        // xin(s)/xchk ready
            if (s >= 4) BAR_SYNC(B_FR0 + (s & 3), CNT_RI); // gin[s&3] free

            if (itid < 204) {
                float* gq = gin + (s & 3) * 2 * GSZ + kh * GSZ;
                if (role > 0) {
                    const ulonglong2* sp =
                        (const ulonglong2*)(xin + (s & (XBUF - 1)) * 416 + kb * BT);
                    ull a00 = biasA, a01 = biasA, a02 = biasA, a03 = biasA;
                    ull a10 = biasB, a11 = biasB, a12 = biasB, a13 = biasB;
                    #pragma unroll
                    for (int kk = 0; kk < 26; kk++) {
                        ulonglong2 S0 = sp[2 * kk], S1 = sp[2 * kk + 1];
                        ull q0 = splat2(w0[kk]);
                        ull q1 = splat2(w1[kk]);
                        a00 = ffma2(S0.x, q0, a00); a01 = ffma2(S0.y, q0, a01);
                        a02 = ffma2(S1.x, q0, a02); a03 = ffma2(S1.y, q0, a03);
                        a10 = ffma2(S0.x, q1, a10); a11 = ffma2(S0.y, q1, a11);
                        a12 = ffma2(S1.x, q1, a12); a13 = ffma2(S1.y, q1, a13);
                    }
                    ulonglong2 v;
                    float* gw = gq + r0 * BT;
                    v.x = a00; v.y = a01; *(ulonglong2*)(gw)          = v;
                    v.x = a02; v.y = a03; *(ulonglong2*)(gw + 4)      = v;
                    v.x = a10; v.y = a11; *(ulonglong2*)(gw + BT)     = v;
                    v.x = a12; v.y = a13; *(ulonglong2*)(gw + BT + 4) = v;
                } else if (kh == 0) {   // role 0 rank-1 input term
                    const ulonglong2* xp =
                        (const ulonglong2*)(xchk + ((s >> 5) & 1) * 256 + (s & 31) * 8);
                    ulonglong2 X0 = xp[0], X1 = xp[1];
                    ull a0 = ffma2(X0.x, w1A, biasA);
                    ull a1 = ffma2(X0.y, w1A, biasA);
                    ull a2 = ffma2(X1.x, w1A, biasA);
                    ull a3 = ffma2(X1.y, w1A, biasA);
                    ull b0 = ffma2(X0.x, w1B, biasB);
                    ull b1 = ffma2(X0.y, w1B, biasB);
                    ull b2 = ffma2(X1.x, w1B, biasB);
                    ull b3 = ffma2(X1.y, w1B, biasB);
                    ulonglong2 v;
                    float* gw = gq + r0 * BT;
                    v.x = a0; v.y = a1; *(ulonglong2*)(gw)          = v;
                    v.x = a2; v.y = a3; *(ulonglong2*)(gw + 4)      = v;
                    v.x = b0; v.y = b1; *(ulonglong2*)(gw + BT)     = v;
                    v.x = b2; v.y = b3; *(ulonglong2*)(gw + BT + 4) = v;
                }
            }
            MEMBAR_CTA();
            BAR_ARRIVE(B_IN0 + (s & 3), CNT_RI);   // gin(s) ready
        }
    } else {
        // ================ comm warp (warp 0: lowest priority) =============
        const int lane = tid;
        for (int k = 0; k < TN; k++) {
            BAR_SYNC(B_XC, CNT_XC);
            if (role > 0 && k + DPRE < TN) {
                if (lane == 0) wait_ge(&g_prod[role - 1][g], (unsigned)(k + DPRE + 1));
                __syncwarp();
                const float4* s4 =
                    (const float4*)(ring_in + ((k + DPRE) & (NSLOT - 1)) * EBT);
                float4* d4 = (float4*)(xin + ((k + DPRE) & (XBUF - 1)) * 416);
                for (int i = lane; i < EBT / 4; i += 32) d4[i] = ldcg4(s4 + i);
                __syncwarp();
                if (lane == 0) st_rel(&g_cons[role - 1][g], (unsigned)(k + DPRE + 1));
            }
            if (role == 0 && (k & 31) == 0 && k + 32 < TN) {
                const int w = ((k >> 5) + 1) & 1;
                #pragma unroll
                for (int b = 0; b < BT; b++)
                    xchk[w * 256 + lane * 8 + b] =
                        x[(size_t)(g * BT + b) * TN + (k + 32 + lane)];
            }
        }
    }
}

extern "C" void kernel_launch(void* const* d_in, const int* in_sizes, int n_in,
                              void* d_out, int out_size)
{
    (void)in_sizes; (void)n_in; (void)out_size;
    const float* x    = (const float*)d_in[0];
    const float* Wih1 = (const float*)d_in[1];
    const float* Whh1 = (const float*)d_in[2];
    const float* bih1 = (const float*)d_in[3];
    const float* bhh1 = (const float*)d_in[4];
    const float* Wih  = (const float*)d_in[5];
    const float* Whh  = (const float*)d_in[6];
    const float* bih  = (const float*)d_in[7];
    const float* bhh  = (const float*)d_in[8];
    const float* Wl   = (const float*)d_in[9];
    const float* bl   = (const float*)d_in[10];
    float* out = (float*)d_out;

    const int smem_bytes = 20628 * 4;  // 82512
    cudaFuncSetAttribute(lstm_kernel, cudaFuncAttributeMaxDynamicSharedMemorySize,
                         smem_bytes);

    reset_kernel<<<1, 64>>>();
    lstm_kernel<<<3 * NG, NTH, smem_bytes>>>(x, Wih1, Whh1, bih1, bhh1,
                                             Wih, Whh, bih, bhh, Wl, bl, out);
}

// round 17
// speedup vs baseline: 1.2033x; 1.2033x over previous
#include <cuda_runtime.h>

// ---------------------------------------------------------------------------
// 5-layer stacked LSTM, H=51, B=256, T=2048. Output depends only on layer-3 h
// => layers 4,5 dead. 3 roles (L1,L2,L3) x 32 batch groups = 96 CTAs.
// R15 structure with ARBITER-PRIORITY REMAP (hi-wid-first scheduler):
//   comm warp (warp 0):   ring prefetch D=4 (latency-tolerant -> lowest prio)
//   I group (warps 1-7):  input GEMV(s), 2 rows x half-k per lane
//   R group (warps 8-14): recurrent GEMV(t) -> cell(t)  [serial chain -> TOP prio]
// gin 2 partials, 4-deep I->R handoff, tanh.approx (sigmoid x/2 folded),
// c in registers. Dataflow identical to R15; only warp roles permuted.
// ---------------------------------------------------------------------------

#define HN 51
#define NJ 204
#define TN 2048
#define NG 32
#define BT 8
#define NSLOT 16
#define XBUF 8
#define DPRE 4
#define NTH 480
#define IB   32               // first tid of I group  (warps 1-7)
#define RB   256              // first tid of R group  (warps 8-14)
#define EBT  408              // HN*BT
#define GSZ  1632             // NJ*BT

// named barrier ids / counts
#define B_IN0 2               // ids 2..5  : gin(s) ready     (I arrive, R sync)
#define B_FR0 6               // ids 6..9  : gin slot free    (R arrive, I sync)
#define B_RH  10              // R-internal: h(t) complete
#define B_XC  11              // I+comm pacing
#define CNT_RI 448
#define CNT_R  224
#define CNT_XC 256

typedef unsigned long long ull;

__device__ float    g_hbuf[2][NG][NSLOT][EBT];
__device__ unsigned g_prod[2][NG];
__device__ unsigned g_cons[2][NG];

__device__ __forceinline__ unsigned ld_acq(const unsigned* p) {
    unsigned v;
    asm volatile("ld.global.acquire.gpu.u32 %0, [%1];" : "=r"(v) : "l"(p));
    return v;
}
__device__ __forceinline__ void st_rel(unsigned* p, unsigned v) {
    asm volatile("st.global.release.gpu.u32 [%0], %1;" :: "l"(p), "r"(v));
}
__device__ __forceinline__ void wait_ge(unsigned* p, unsigned v) {
    if (ld_acq(p) >= v) return;
    while (ld_acq(p) < v) __nanosleep(32);
}
__device__ __forceinline__ float4 ldcg4(const float4* p) {
    float4 v;
    asm volatile("ld.global.cg.v4.f32 {%0,%1,%2,%3}, [%4];"
                 : "=f"(v.x), "=f"(v.y), "=f"(v.z), "=f"(v.w) : "l"(p));
    return v;
}
__device__ __forceinline__ ull ffma2(ull a, ull b, ull c) {
    ull d;
    asm("fma.rn.f32x2 %0, %1, %2, %3;" : "=l"(d) : "l"(a), "l"(b), "l"(c));
    return d;
}
__device__ __forceinline__ ull splat2(float x) {
    ull d; unsigned u = __float_as_uint(x);
    asm("mov.b64 %0, {%1, %2};" : "=l"(d) : "r"(u), "r"(u));
    return d;
}
__device__ __forceinline__ float tanha(float x) {
    float y;
    asm("tanh.approx.f32 %0, %1;" : "=f"(y) : "f"(x));
    return y;
}
__device__ __forceinline__ float sig_h(float y) {   // arg pre-halved
    return fmaf(0.5f, tanha(y), 0.5f);
}
#define BAR_SYNC(id, cnt)   asm volatile("bar.sync %0, %1;"   :: "r"(id), "r"(cnt) : "memory")
#define BAR_ARRIVE(id, cnt) asm volatile("bar.arrive %0, %1;" :: "r"(id), "r"(cnt) : "memory")
#define MEMBAR_CTA()        asm volatile("membar.cta;" ::: "memory")

__global__ void __launch_bounds__(64, 1) reset_kernel() {
    int i = threadIdx.x;
    if (i < NG) {
        g_prod[0][i] = 0; g_prod[1][i] = 0;
        g_cons[0][i] = 0; g_cons[1][i] = 0;
    }
}

__global__ void __launch_bounds__(NTH, 1) lstm_kernel(
    const float* __restrict__ x,    const float* __restrict__ Wih1,
    const float* __restrict__ Whh1, const float* __restrict__ bih1,
    const float* __restrict__ bhh1, const float* __restrict__ Wih,
    const float* __restrict__ Whh,  const float* __restrict__ bih,
    const float* __restrict__ bhh,  const float* __restrict__ Wl,
    const float* __restrict__ bl,   float* __restrict__ out)
{
    extern __shared__ float sm[];
    float* grec = sm;                 // [2 kh][GSZ]            3264
    float* gin  = sm + 3264;          // [4 par][2 kh][GSZ]     13056
    float* xin  = sm + 16320;         // [XBUF][52*8]           3328 (row 51 zero)
    float* h_t  = sm + 19648;         // [52*8] (row 51 zero)   416
    float* xchk = sm + 20064;         // [2][32][8]             512
    float* wl_s = sm + 20576;         // [52]
    // total 20628 floats = 82512 bytes

    const int tid  = threadIdx.x;
    const int role = blockIdx.x / NG;   // 0=L1, 1=L2, 2=L3
    const int g    = blockIdx.x % NG;

    const bool is_comm = (tid < IB);          // warp 0
    const bool is_I    = (tid >= IB && tid < RB);   // warps 1-7
    const int  itid    = is_I ? (tid - IB) : 0;     // 0..223
    const int  rtid    = (tid >= RB) ? (tid - RB) : 0;  // 0..223

    // ---------------- group-specific weight loads ----------------
    // Both R and I lanes: 2 gate rows x half-k (26 iters, k=25 overlap zeroed
    // in the kh=1 half). i,f,o rows pre-scaled by 0.5 for tanh-only sigmoid.
    float w0[26], w1[26];
    ull biasA = 0, biasB = 0, w1A = 0, w1B = 0;
    int kb = 0, r0 = 0;

    if (tid >= RB && rtid < 204) {        // R GEMV lane (recurrent weights)
        const int kh = rtid / 102, jp = rtid % 102;
        r0 = 2 * jp; kb = kh * 25;
        const float* W = (role == 0) ? Whh1 : (Whh + (role - 1) * NJ * HN);
        const float sc0 = ((r0     / 51) == 2) ? 1.f : 0.5f;
        const float sc1 = (((r0+1) / 51) == 2) ? 1.f : 0.5f;
        #pragma unroll
        for (int kk = 0; kk < 26; kk++) {
            int k = kb + kk;
            bool z = (kh == 1 && kk == 0);
            w0[kk] = z ? 0.f : sc0 * W[ r0      * HN + k];
            w1[kk] = z ? 0.f : sc1 * W[(r0 + 1) * HN + k];
        }
    } else if (is_I && itid < 204) {      // I GEMV lane (input weights)
        const int kh = itid / 102, jp = itid % 102;
        r0 = 2 * jp; kb = kh * 25;
        const float sc0 = ((r0     / 51) == 2) ? 1.f : 0.5f;
        const float sc1 = (((r0+1) / 51) == 2) ? 1.f : 0.5f;
        if (role > 0) {
            const int l = role - 1;
            const float* W = Wih + l * NJ * HN;
            #pragma unroll
            for (int kk = 0; kk < 26; kk++) {
                int k = kb + kk;
                bool z = (kh == 1 && kk == 0);
                w0[kk] = z ? 0.f : sc0 * W[ r0      * HN + k];
                w1[kk] = z ? 0.f : sc1 * W[(r0 + 1) * HN + k];
            }
            if (kh == 0) {
                biasA = splat2(sc0 * (bih[l * NJ + r0]     + bhh[l * NJ + r0]));
                biasB = splat2(sc1 * (bih[l * NJ + r0 + 1] + bhh[l * NJ + r0 + 1]));
            }
        } else if (kh == 0) {   // role 0: rank-1 input term
            w1A   = splat2(sc0 * Wih1[r0]);
            w1B   = splat2(sc1 * Wih1[r0 + 1]);
            biasA = splat2(sc0 * (bih1[r0]     + bhh1[r0]));
            biasB = splat2(sc1 * (bih1[r0 + 1] + bhh1[r0 + 1]));
        }
    }
    const float blv = (role == 2) ? bl[0] : 0.f;

    for (int i = tid; i < 20628; i += NTH) sm[i] = 0.f;
    __syncthreads();
    if (role == 2 && tid < HN) wl_s[tid] = Wl[tid];
    __syncthreads();

    float*       ring_out = (role < 2) ? &g_hbuf[role][g][0][0]     : (float*)0;
    const float* ring_in  = (role > 0) ? &g_hbuf[role - 1][g][0][0] : (const float*)0;

    // ---- prologue: comm warp fills xin slots 0..3 / x window 0 ----
    if (is_comm) {
        const int lane = tid;
        if (role > 0) {
            for (int d = 0; d < DPRE; d++) {
                if (lane == 0) wait_ge(&g_prod[role - 1][g], (unsigned)(d + 1));
                __syncwarp();
                const float4* s4 = (const float4*)(ring_in + d * EBT);
                float4* d4 = (float4*)(xin + d * 416);
                for (int i = lane; i < EBT / 4; i += 32) d4[i] = ldcg4(s4 + i);
                __syncwarp();
                if (lane == 0) st_rel(&g_cons[role - 1][g], (unsigned)(d + 1));
            }
        } else {
            #pragma unroll
            for (int b = 0; b < BT; b++)
                xchk[lane * 8 + b] = x[(size_t)(g * BT + b) * TN + lane];
        }
    }
    __syncthreads();

    // =====================================================================
    if (tid >= RB) {
        // ============= R group (warps 8-14: TOP arbiter priority) =========
        float c_a = 0.f, c_b = 0.f;
        const int  kh = (rtid < 204) ? rtid / 102 : 0;
        const bool lane_out = (role == 2) && (rtid >= 204 && rtid < 212);
        const bool lane_bp  = (role <  2) && (rtid == 212);

        for (int t = 0; t < TN; t++) {
            // ---- recurrent GEMV(t) over h(t-1) ----
            if (rtid < 204) {
                const ulonglong2* hp = (const ulonglong2*)(h_t + kb * BT);
                ull a00 = 0, a01 = 0, a02 = 0, a03 = 0;
                ull a10 = 0, a11 = 0, a12 = 0, a13 = 0;
                #pragma unroll
                for (int kk = 0; kk < 26; kk++) {
                    ulonglong2 S0 = hp[2 * kk], S1 = hp[2 * kk + 1];
                    ull q0 = splat2(w0[kk]);
                    ull q1 = splat2(w1[kk]);
                    a00 = ffma2(S0.x, q0, a00); a01 = ffma2(S0.y, q0, a01);
                    a02 = ffma2(S1.x, q0, a02); a03 = ffma2(S1.y, q0, a03);
                    a10 = ffma2(S0.x, q1, a10); a11 = ffma2(S0.y, q1, a11);
                    a12 = ffma2(S1.x, q1, a12); a13 = ffma2(S1.y, q1, a13);
                }
                float* gr = grec + kh * GSZ + r0 * BT;
                ulonglong2 s;
                s.x = a00; s.y = a01; *(ulonglong2*)(gr)          = s;
                s.x = a02; s.y = a03; *(ulonglong2*)(gr + 4)      = s;
                s.x = a10; s.y = a11; *(ulonglong2*)(gr + BT)     = s;
                s.x = a12; s.y = a13; *(ulonglong2*)(gr + BT + 4) = s;
            } else {
                if (lane_out && t > 0) {                 // out(t-1) from h(t-1)
                    const int b = rtid - 204;
                    float a = blv;
                    #pragma unroll
                    for (int u = 0; u < HN; u++) a += h_t[u * BT + b] * wl_s[u];
                    out[(size_t)(g * BT + b) * TN + (t - 1)] = a;
                }
                if (lane_bp && t >= NSLOT)
                    wait_ge(&g_cons[role][g], (unsigned)(t - (NSLOT - 1)));
            }

            BAR_SYNC(B_IN0 + (t & 3), CNT_RI);   // gin(t) ready; grec drained

            // ---- cell(t): elements rtid and rtid+224 (16 LDS/elem) ----
            {
                const float* gi = gin + (t & 3) * 2 * GSZ;
                float* rslot = (role < 2) ? (ring_out + (t & (NSLOT - 1)) * EBT)
                                          : (float*)0;
                {
                    const int e = rtid;
                    float yi = (grec[e]        + grec[GSZ + e])
                             + (gi[e]          + gi[GSZ + e]);
                    float yf = (grec[408 + e]  + grec[GSZ + 408 + e])
                             + (gi[408 + e]    + gi[GSZ + 408 + e]);
                    float gg = (grec[816 + e]  + grec[GSZ + 816 + e])
                             + (gi[816 + e]    + gi[GSZ + 816 + e]);
                    float yo = (grec[1224 + e] + grec[GSZ + 1224 + e])
                             + (gi[1224 + e]   + gi[GSZ + 1224 + e]);
                    float c = sig_h(yf) * c_a + sig_h(yi) * tanha(gg);
                    float h = sig_h(yo) * tanha(c);
                    c_a = c; h_t[e] = h;
                    if (role < 2) rslot[e] = h;
                }
                if (rtid < 184) {
                    const int e = rtid + 224;
                    float yi = (grec[e]        + grec[GSZ + e])
                             + (gi[e]          + gi[GSZ + e]);
                    float yf = (grec[408 + e]  + grec[GSZ + 408 + e])
                             + (gi[408 + e]    + gi[GSZ + 408 + e]);
                    float gg = (grec[816 + e]  + grec[GSZ + 816 + e])
                             + (gi[816 + e]    + gi[GSZ + 816 + e]);
                    float yo = (grec[1224 + e] + grec[GSZ + 1224 + e])
                             + (gi[1224 + e]   + gi[GSZ + 1224 + e]);
                    float c = sig_h(yf) * c_b + sig_h(yi) * tanha(gg);
                    float h = sig_h(yo) * tanha(c);
                    c_b = c; h_t[e] = h;
                    if (role < 2) rslot[e] = h;
                }
            }

            BAR_ARRIVE(B_FR0 + (t & 3), CNT_RI); // gin slot (t&3) consumed
            BAR_SYNC(B_RH, CNT_R);               // h(t) + ring STGs complete
            if (role < 2 && rtid == 0) st_rel(&g_prod[role][g], (unsigned)(t + 1));
        }
        // epilogue: out(TN-1)
        if (lane_out) {
            const int b = rtid - 204;
            float a = blv;
            #pragma unroll
            for (int u = 0; u < HN; u++) a += h_t[u * BT + b] * wl_s[u];
            out[(size_t)(g * BT + b) * TN + (TN - 1)] = a;
        }
    } else if (is_I) {
        // ================ I group (warps 1-7) =============================
        const int kh = (itid < 204) ? itid / 102 : 0;

        for (int s = 0; s < TN; s++) {
            BAR_SYNC(B_XC, CNT_XC);                        // xin(s)/xchk ready
            if (s >= 4) BAR_SYNC(B_FR0 + (s & 3), CNT_RI); // gin[s&3] free

            if (itid < 204) {
                float* gq = gin + (s & 3) * 2 * GSZ + kh * GSZ;
                if (role > 0) {
                    const ulonglong2* sp =
                        (const ulonglong2*)(xin + (s & (XBUF - 1)) * 416 + kb * BT);
                    ull a00 = biasA, a01 = biasA, a02 = biasA, a03 = biasA;
                    ull a10 = biasB, a11 = biasB, a12 = biasB, a13 = biasB;
                    #pragma unroll
                    for (int kk = 0; kk < 26; kk++) {
                        ulonglong2 S0 = sp[2 * kk], S1 = sp[2 * kk + 1];
                        ull q0 = splat2(w0[kk]);
                        ull q1 = splat2(w1[kk]);
                        a00 = ffma2(S0.x, q0, a00); a01 = ffma2(S0.y, q0, a01);
                        a02 = ffma2(S1.x, q0, a02); a03 = ffma2(S1.y, q0, a03);
                        a10 = ffma2(S0.x, q1, a10); a11 = ffma2(S0.y, q1, a11);
                        a12 = ffma2(S1.x, q1, a12); a13 = ffma2(S1.y, q1, a13);
                    }
                    ulonglong2 v;
                    float* gw = gq + r0 * BT;
                    v.x = a00; v.y = a01; *(ulonglong2*)(gw)          = v;
                    v.x = a02; v.y = a03; *(ulonglong2*)(gw + 4)      = v;
                    v.x = a10; v.y = a11; *(ulonglong2*)(gw + BT)     = v;
                    v.x = a12; v.y = a13; *(ulonglong2*)(gw + BT + 4) = v;
                } else if (kh == 0) {   // role 0 rank-1 input term
                    const ulonglong2* xp =
                        (const ulonglong2*)(xchk + ((s >> 5) & 1) * 256 + (s & 31) * 8);
                    ulonglong2 X0 = xp[0], X1 = xp[1];
                    ull a0 = ffma2(X0.x, w1A, biasA);
                    ull a1 = ffma2(X0.y, w1A, biasA);
                    ull a2 = ffma2(X1.x, w1A, biasA);
                    ull a3 = ffma2(X1.y, w1A, biasA);
                    ull b0 = ffma2(X0.x, w1B, biasB);
                    ull b1 = ffma2(X0.y, w1B, biasB);
                    ull b2 = ffma2(X1.x, w1B, biasB);
                    ull b3 = ffma2(X1.y, w1B, biasB);
                    ulonglong2 v;
                    float* gw = gq + r0 * BT;
                    v.x = a0; v.y = a1; *(ulonglong2*)(gw)          = v;
                    v.x = a2; v.y = a3; *(ulonglong2*)(gw + 4)      = v;
                    v.x = b0; v.y = b1; *(ulonglong2*)(gw + BT)     = v;
                    v.x = b2; v.y = b3; *(ulonglong2*)(gw + BT + 4) = v;
                }
            }
            MEMBAR_CTA();
            BAR_ARRIVE(B_IN0 + (s & 3), CNT_RI);   // gin(s) ready
        }
    } else {
        // ================ comm warp (warp 0: lowest priority) =============
        const int lane = tid;
        for (int k = 0; k < TN; k++) {
            BAR_SYNC(B_XC, CNT_XC);
            if (role > 0 && k + DPRE < TN) {
                if (lane == 0) wait_ge(&g_prod[role - 1][g], (unsigned)(k + DPRE + 1));
                __syncwarp();
                const float4* s4 =
                    (const float4*)(ring_in + ((k + DPRE) & (NSLOT - 1)) * EBT);
                float4* d4 = (float4*)(xin + ((k + DPRE) & (XBUF - 1)) * 416);
                for (int i = lane; i < EBT / 4; i += 32) d4[i] = ldcg4(s4 + i);
                __syncwarp();
                if (lane == 0) st_rel(&g_cons[role - 1][g], (unsigned)(k + DPRE + 1));
            }
            if (role == 0 && (k & 31) == 0 && k + 32 < TN) {
                const int w = ((k >> 5) + 1) & 1;
                #pragma unroll
                for (int b = 0; b < BT; b++)
                    xchk[w * 256 + lane * 8 + b] =
                        x[(size_t)(g * BT + b) * TN + (k + 32 + lane)];
            }
        }
    }
}

extern "C" void kernel_launch(void* const* d_in, const int* in_sizes, int n_in,
                              void* d_out, int out_size)
{
    (void)in_sizes; (void)n_in; (void)out_size;
    const float* x    = (const float*)d_in[0];
    const float* Wih1 = (const float*)d_in[1];
    const float* Whh1 = (const float*)d_in[2];
    const float* bih1 = (const float*)d_in[3];
    const float* bhh1 = (const float*)d_in[4];
    const float* Wih  = (const float*)d_in[5];
    const float* Whh  = (const float*)d_in[6];
    const float* bih  = (const float*)d_in[7];
    const float* bhh  = (const float*)d_in[8];
    const float* Wl   = (const float*)d_in[9];
    const float* bl   = (const float*)d_in[10];
    float* out = (float*)d_out;

    const int smem_bytes = 20628 * 4;  // 82512
    cudaFuncSetAttribute(lstm_kernel, cudaFuncAttributeMaxDynamicSharedMemorySize,
                         smem_bytes);

    reset_kernel<<<1, 64>>>();
    lstm_kernel<<<3 * NG, NTH, smem_bytes>>>(x, Wih1, Whh1, bih1, bhh1,
                                             Wih, Whh, bih, bhh, Wl, bl, out);
}